// round 11
// baseline (speedup 1.0000x reference)
#include <cuda_runtime.h>
#include <cstdint>

#define BATCH 8
#define CCH   48
#define NPIX  4096
#define NB    32768
#define KNN   9

// ---------------- device scratch ----------------
__device__ float  g_xt [BATCH * CCH * NPIX];   // normalized, k-major (B tiles)
__device__ float2 g_xtd[BATCH * CCH * NPIX];   // normalized, duplicated pairs (A tiles)
__device__ float4 g_nodes[NB * 12];            // raw, node-major (k5)
__device__ float  g_sq[NB];                    // sum(xn^2)
__device__ int    g_knn[NB * KNN];
__device__ int    g_deg[NB];

// ---------------- helpers ----------------
__device__ __forceinline__ uint32_t smem_u32(const void* p) {
    uint32_t a;
    asm("{ .reg .u64 t; cvta.to.shared.u64 t, %1; cvt.u32.u64 %0, t; }" : "=r"(a) : "l"(p));
    return a;
}
__device__ __forceinline__ void cp16(uint32_t dst, const void* src) {
    asm volatile("cp.async.cg.shared.global [%0], [%1], 16;" :: "r"(dst), "l"(src));
}
__device__ __forceinline__ void cp4(uint32_t dst, const void* src) {
    asm volatile("cp.async.ca.shared.global [%0], [%1], 4;" :: "r"(dst), "l"(src));
}
__device__ __forceinline__ void cp_commit() { asm volatile("cp.async.commit_group;"); }
template <int N> __device__ __forceinline__ void cp_wait() {
    asm volatile("cp.async.wait_group %0;" :: "n"(N));
}
__device__ __forceinline__ unsigned long long ffma2(unsigned long long a,
                                                    unsigned long long b,
                                                    unsigned long long c) {
    unsigned long long d;
    asm("fma.rn.f32x2 %0, %1, %2, %3;" : "=l"(d) : "l"(a), "l"(b), "l"(c));
    return d;
}
__device__ __forceinline__ unsigned long long packdup(float x) {
    unsigned long long d;
    asm("mov.b64 %0, {%1, %1};" : "=l"(d) : "f"(x));
    return d;
}
__device__ __forceinline__ void unpack2(unsigned long long v, float& lo, float& hi) {
    asm("mov.b64 {%0, %1}, %2;" : "=f"(lo), "=f"(hi) : "l"(v));
}

// ---------------- k2 smem layout (bytes) ----------------
#define OFF_A    0                        // dup A: 48k x 64 rowpairs x 16B = 49152
#define OFF_B    49152                    // 2 x (48k x 128 cols x 4B) = 49152
#define OFF_SQ   98304                    // 2 x 512
#define SMEM_K2  99328
// merge scratch overlays OFF_B after the main loop (B dead by then)

// ======================================================================
// K1: normalize; emit g_xt / g_xtd (k-major), g_nodes, sq, deg=0.
// ======================================================================
__global__ __launch_bounds__(128) void k1_normalize(const float* __restrict__ x) {
    __shared__ float s[128 * 49];
    __shared__ float s_mn[128];
    const int tid  = threadIdx.x;
    const int n0g  = blockIdx.x * 128;
    const int b    = n0g >> 12;
    const int nloc = n0g & (NPIX - 1);

    const float* xb = x + (size_t)b * CCH * NPIX + nloc;
    #pragma unroll
    for (int c = 0; c < CCH; c++)
        s[tid * 49 + c] = xb[(size_t)c * NPIX + tid];

    float ss = 0.f;
    #pragma unroll
    for (int c = 0; c < CCH; c++) { float v = s[tid * 49 + c]; ss += v * v; }
    float mn = fmaxf(sqrtf(ss), 1e-12f);
    s_mn[tid] = mn;
    float sqv = 0.f;
    #pragma unroll
    for (int c = 0; c < CCH; c++) { float v = s[tid * 49 + c] / mn; sqv += v * v; }
    g_sq[n0g + tid]  = sqv;
    g_deg[n0g + tid] = 0;
    __syncthreads();

    #pragma unroll
    for (int c = 0; c < CCH; c++) {
        const float v = s[tid * 49 + c] / s_mn[tid];
        const int   a = (b * CCH + c) * NPIX + nloc + tid;
        g_xt[a]  = v;
        g_xtd[a] = make_float2(v, v);
    }

    float* nodes_f = (float*)g_nodes;
    #pragma unroll
    for (int it = 0; it < 48; it++) {
        int idx = it * 128 + tid;
        int q = idx / 48, rr = idx - q * 48;
        nodes_f[(size_t)n0g * 48 + idx] = s[q * 49 + rr];
    }
}

// ======================================================================
// K2: fp32x2 GEMM, thread = 2 adjacent rows x 32 cols (1 LDS.128 for A,
//     8 broadcast LDS.128 for B per k => 9 LDS : 32 FFMA2, fma-bound).
//     Register-resident exact top-9 per (row, col-quarter); 4-way merge.
// ======================================================================
__global__ __launch_bounds__(256, 2) void k2_knn() {
    extern __shared__ __align__(16) char smem[];
    const int tid = threadIdx.x;
    const int p   = tid & 63;            // rowpair (rows 2p, 2p+1)
    const int q   = tid >> 6;            // column quarter (warp-uniform)
    const int b   = blockIdx.x >> 5;
    const int rt  = blockIdx.x & 31;
    const int rowbase = b * NPIX + rt * 128;
    const uint32_t sb = smem_u32(smem);

    // prologue: A-dup strip + B tile 0 + sq0
    {
        #pragma unroll
        for (int i = 0; i < 12; i++) {
            const int c = tid + i * 256;          // 3072 chunks of 16B
            const int k = c >> 6, rp = c & 63;
            cp16(sb + OFF_A + (uint32_t)(k * 1024 + rp * 16),
                 g_xtd + (size_t)(b * CCH + k) * NPIX + rt * 128 + rp * 2);
        }
        #pragma unroll
        for (int i = 0; i < 6; i++) {
            const int c = tid + i * 256;          // 1536 chunks
            const int k = c >> 5, pp = c & 31;
            cp16(sb + OFF_B + (uint32_t)(k * 512 + pp * 16),
                 g_xt + (size_t)(b * CCH + k) * NPIX + pp * 4);
        }
        if (tid < 128) cp4(sb + OFF_SQ + tid * 4, g_sq + b * NPIX + tid);
        cp_commit();
    }

    // register top-9 per row (ascending), strict < keeps lowest col on ties
    float d9[2][KNN]; int i9[2][KNN];
    #pragma unroll
    for (int r = 0; r < 2; r++)
        #pragma unroll
        for (int k = 0; k < KNN; k++) {
            d9[r][k] = __int_as_float(0x7f800000);
            i9[r][k] = 0x7fffffff;
        }
    const unsigned long long NEG2 = packdup(-2.0f);

    #pragma unroll 1
    for (int t = 0; t < 32; t++) {
        const int buf = t & 1;
        cp_wait<0>();
        __syncthreads();

        if (t < 31) {
            const int col0 = (t + 1) * 128;
            const uint32_t dstB = sb + OFF_B + (buf ^ 1) * 24576;
            #pragma unroll
            for (int i = 0; i < 6; i++) {
                const int c = tid + i * 256;
                const int k = c >> 5, pp = c & 31;
                cp16(dstB + (uint32_t)(k * 512 + pp * 16),
                     g_xt + (size_t)(b * CCH + k) * NPIX + col0 + pp * 4);
            }
            if (tid < 128) cp4(sb + OFF_SQ + (buf ^ 1) * 512 + tid * 4,
                               g_sq + b * NPIX + col0 + tid);
            cp_commit();
        }

        // ---- GEMM: C[2 rows][8 chunks][2 pairs], K=48 ----
        unsigned long long C[2][8][2];
        #pragma unroll
        for (int ch = 0; ch < 8; ch++) {
            C[0][ch][0] = 0ull; C[0][ch][1] = 0ull;
            C[1][ch][0] = 0ull; C[1][ch][1] = 0ull;
        }

        const char* Abase = smem + OFF_A + (uint32_t)p * 16;
        const char* Bbase = smem + OFF_B + buf * 24576 + (uint32_t)q * 128;
        #pragma unroll 8
        for (int k = 0; k < 48; k++) {
            const ulonglong2 a2 = *(const ulonglong2*)(Abase + k * 1024);
            const char* bk = Bbase + k * 512;
            #pragma unroll
            for (int ch = 0; ch < 8; ch++) {
                const ulonglong2 bv = *(const ulonglong2*)(bk + ch * 16);
                C[0][ch][0] = ffma2(a2.x, bv.x, C[0][ch][0]);
                C[0][ch][1] = ffma2(a2.x, bv.y, C[0][ch][1]);
                C[1][ch][0] = ffma2(a2.y, bv.x, C[1][ch][0]);
                C[1][ch][1] = ffma2(a2.y, bv.y, C[1][ch][1]);
            }
        }

        // ---- epilogue: two-pass (min-fold screen; rare recompute+insert) ----
        const char* sqb = smem + OFF_SQ + buf * 512 + (uint32_t)q * 128;
        const int gbase = b * NPIX + t * 128 + q * 32;
        #pragma unroll
        for (int r = 0; r < 2; r++) {
            float rowmin = __int_as_float(0x7f800000);
            #pragma unroll
            for (int ch = 0; ch < 8; ch++) {
                const ulonglong2 s2 = *(const ulonglong2*)(sqb + ch * 16);
                float l0, h0, l1, h1;
                unpack2(ffma2(C[r][ch][0], NEG2, s2.x), l0, h0);
                unpack2(ffma2(C[r][ch][1], NEG2, s2.y), l1, h1);
                rowmin = fminf(rowmin, fminf(fminf(l0, h0), fminf(l1, h1)));
            }
            if (rowmin < d9[r][KNN - 1]) {
                #pragma unroll
                for (int ch = 0; ch < 8; ch++) {
                    const ulonglong2 s2 = *(const ulonglong2*)(sqb + ch * 16);
                    float dv[4];
                    unpack2(ffma2(C[r][ch][0], NEG2, s2.x), dv[0], dv[1]);
                    unpack2(ffma2(C[r][ch][1], NEG2, s2.y), dv[2], dv[3]);
                    #pragma unroll
                    for (int e = 0; e < 4; e++) {
                        if (dv[e] < d9[r][KNN - 1]) {
                            float cd = dv[e]; int ci = gbase + ch * 4 + e;
                            #pragma unroll
                            for (int sl = 0; sl < KNN; sl++) {
                                const bool sw = cd < d9[r][sl];
                                const float td = d9[r][sl]; const int ti = i9[r][sl];
                                d9[r][sl] = sw ? cd : td;  i9[r][sl] = sw ? ci : ti;
                                cd        = sw ? td : cd;  ci        = sw ? ti : ci;
                            }
                        }
                    }
                }
            }
        }
    }

    // ---- 4-way merge of quarter lists (scratch overlays dead B buffer) ----
    __syncthreads();
    float* sc_d = (float*)(smem + OFF_B);                      // [row][q][9]
    int*   sc_i = (int*)(smem + OFF_B + 128 * 4 * KNN * 4);
    #pragma unroll
    for (int r = 0; r < 2; r++)
        #pragma unroll
        for (int k = 0; k < KNN; k++) {
            sc_d[((2 * p + r) * 4 + q) * KNN + k] = d9[r][k];
            sc_i[((2 * p + r) * 4 + q) * KNN + k] = i9[r][k];
        }
    __syncthreads();

    if (tid < 128) {
        const int gr = rowbase + tid;
        int h[4] = {0, 0, 0, 0};
        #pragma unroll
        for (int k = 0; k < KNN; k++) {
            float bd = __int_as_float(0x7f800000);
            int   bi = 0x7fffffff, bq = 0;
            #pragma unroll
            for (int qq = 0; qq < 4; qq++) {
                const float dd = sc_d[(tid * 4 + qq) * KNN + h[qq]];
                const int   ii = sc_i[(tid * 4 + qq) * KNN + h[qq]];
                if (dd < bd || (dd == bd && ii < bi)) { bd = dd; bi = ii; bq = qq; }
            }
            g_knn[(size_t)gr * KNN + k] = bi;
            if (!(gr == NB - 1 && k == KNN - 1))
                atomicAdd(&g_deg[bi], 1);
            h[bq]++;
        }
    }
}

// ======================================================================
// K5: fused Tx1 gather + both GEMMs + bias.
// ======================================================================
__global__ __launch_bounds__(192) void k5_output(const float* __restrict__ W0,
                                                 const float* __restrict__ W1,
                                                 const float* __restrict__ bias,
                                                 float* __restrict__ out) {
    const int node0 = blockIdx.x * 4;
    const int ln = threadIdx.x / 48;
    const int c  = threadIdx.x - ln * 48;
    const int i  = node0 + ln;

    __shared__ float t1[4][48];
    __shared__ int   ssrc[4][KNN];
    __shared__ float sdi[4][KNN];

    if (threadIdx.x < 4 * KNN) {
        const int l = threadIdx.x / KNN, k = threadIdx.x - l * KNN;
        const int e = (node0 + l) * KNN + k;
        const int s = g_knn[e];
        ssrc[l][k] = s;
        float di = 0.f;
        const int dg = g_deg[s];
        if (dg > 0 && e != NB * KNN - 1) di = rsqrtf((float)dg);
        sdi[l][k] = di;
    }
    __syncthreads();

    const float* nodes = (const float*)g_nodes;
    float acc = 0.f;
    #pragma unroll
    for (int k = 0; k < KNN; k++)
        acc += sdi[ln][k] * nodes[(size_t)ssrc[ln][k] * 48 + c];

    const int dgi = g_deg[i];
    const float dinv_i = (dgi > 0) ? rsqrtf((float)dgi) : 0.f;
    t1[ln][c] = -dinv_i * acc;
    __syncthreads();

    float o = bias[c];
    const float* nrow = nodes + (size_t)i * 48;
    #pragma unroll
    for (int cc = 0; cc < 48; cc++)
        o += nrow[cc] * W0[cc * 48 + c] + t1[ln][cc] * W1[cc * 48 + c];
    out[(size_t)i * 48 + c] = o;
}

// ======================================================================
extern "C" void kernel_launch(void* const* d_in, const int* in_sizes, int n_in,
                              void* d_out, int out_size) {
    const float* x    = (const float*)d_in[0];
    const float* W0   = (const float*)d_in[1];
    const float* W1   = (const float*)d_in[2];
    const float* bias = (const float*)d_in[3];
    float* out = (float*)d_out;

    cudaFuncSetAttribute(k2_knn, cudaFuncAttributeMaxDynamicSharedMemorySize, SMEM_K2);

    k1_normalize<<<NB / 128, 128>>>(x);
    k2_knn<<<BATCH * 32, 256, SMEM_K2>>>();
    k5_output<<<NB / 4, 192>>>(W0, W1, bias, out);
}

// round 12
// speedup vs baseline: 1.3441x; 1.3441x over previous
#include <cuda_runtime.h>
#include <cuda_fp16.h>
#include <cstdint>

#define BATCH 8
#define CCH   48
#define NPIX  4096
#define NB    32768
#define KNN   9

// ---------------- device scratch ----------------
__device__ float4   g_xn[NB * 12];     // normalized fp32 (exact rerank)
__device__ float4   g_nodes[NB * 12];  // raw (k5)
__device__ float    g_sq[NB];          // sum(xn^2)
__device__ uint32_t g_h16[NB * 48];    // per node: 24 half2 hi | 24 half2 lo (192B)
__device__ int      g_candi[NB * 36];  // [row][tig 0..3][9]
__device__ int      g_knn[NB * KNN];
__device__ int      g_deg[NB];

// ---------------- helpers ----------------
__device__ __forceinline__ uint32_t smem_u32(const void* p) {
    uint32_t a;
    asm("{ .reg .u64 t; cvta.to.shared.u64 t, %1; cvt.u32.u64 %0, t; }" : "=r"(a) : "l"(p));
    return a;
}
__device__ __forceinline__ void cp16(uint32_t dst, const void* src) {
    asm volatile("cp.async.cg.shared.global [%0], [%1], 16;" :: "r"(dst), "l"(src));
}
__device__ __forceinline__ void cp4(uint32_t dst, const void* src) {
    asm volatile("cp.async.ca.shared.global [%0], [%1], 4;" :: "r"(dst), "l"(src));
}
__device__ __forceinline__ void cp_commit() { asm volatile("cp.async.commit_group;"); }
template <int N> __device__ __forceinline__ void cp_wait() {
    asm volatile("cp.async.wait_group %0;" :: "n"(N));
}
__device__ __forceinline__ void ldsm4(uint32_t* R, uint32_t addr) {
    asm volatile("ldmatrix.sync.aligned.m8n8.x4.shared.b16 {%0,%1,%2,%3}, [%4];"
                 : "=r"(R[0]), "=r"(R[1]), "=r"(R[2]), "=r"(R[3]) : "r"(addr));
}
__device__ __forceinline__ void mma16816(float* C, const uint32_t* A, uint32_t b0, uint32_t b1) {
    asm volatile("mma.sync.aligned.m16n8k16.row.col.f32.f16.f16.f32 "
                 "{%0,%1,%2,%3}, {%4,%5,%6,%7}, {%8,%9}, {%0,%1,%2,%3};"
                 : "+f"(C[0]), "+f"(C[1]), "+f"(C[2]), "+f"(C[3])
                 : "r"(A[0]), "r"(A[1]), "r"(A[2]), "r"(A[3]), "r"(b0), "r"(b1));
}
// register carry-chain sorted insert (strict <, ascending-col call order => stable)
__device__ __forceinline__ void rins(float* d9, int* i9, float d, int idx) {
    float cd = d; int ci = idx;
    #pragma unroll
    for (int sl = 0; sl < KNN; sl++) {
        const bool sw = cd < d9[sl];
        const float td = d9[sl]; const int ti = i9[sl];
        d9[sl] = sw ? cd : td;  i9[sl] = sw ? ci : ti;
        cd     = sw ? td : cd;  ci     = sw ? ti : ci;
    }
}

// ---------------- k2 smem layout (bytes) ----------------
#define OFF_A   0                      // A tile: 128 rows x 240B = 30720
#define OFF_B   30720                  // 2 x 30720
#define OFF_SQ  92160                  // 2 x 512
#define SMEM_K2 93184

// ======================================================================
// K1: normalize; emit g_xn (fp32), g_nodes, g_sq, fp16 hi/lo, deg=0.
// ======================================================================
__global__ __launch_bounds__(128) void k1_normalize(const float* __restrict__ x) {
    __shared__ float s[128 * 49];
    __shared__ float s_mn[128];
    __shared__ float s_rmn[128];
    const int tid  = threadIdx.x;
    const int n0g  = blockIdx.x * 128;
    const int b    = n0g >> 12;
    const int nloc = n0g & (NPIX - 1);

    const float* xb = x + (size_t)b * CCH * NPIX + nloc;
    #pragma unroll
    for (int c = 0; c < CCH; c++)
        s[tid * 49 + c] = xb[(size_t)c * NPIX + tid];

    float ss = 0.f;
    #pragma unroll
    for (int c = 0; c < CCH; c++) { float v = s[tid * 49 + c]; ss += v * v; }
    float mn = fmaxf(sqrtf(ss), 1e-12f);
    s_mn[tid]  = mn;
    s_rmn[tid] = 1.0f / mn;
    float sqv = 0.f;
    #pragma unroll
    for (int c = 0; c < CCH; c++) { float v = s[tid * 49 + c] / mn; sqv += v * v; }
    g_sq[n0g + tid]  = sqv;
    g_deg[n0g + tid] = 0;
    __syncthreads();

    float* nodes_f = (float*)g_nodes;
    float* xn_f    = (float*)g_xn;
    #pragma unroll
    for (int it = 0; it < 48; it++) {
        int idx = it * 128 + tid;
        int q = idx / 48, rr = idx - q * 48;
        float v = s[q * 49 + rr];
        nodes_f[(size_t)n0g * 48 + idx] = v;
        xn_f[(size_t)n0g * 48 + idx]    = v / s_mn[q];
    }
    // fp16 split (hi + residual lo), approx GEMM path only
    #pragma unroll
    for (int it = 0; it < 48; it++) {
        int idx = it * 128 + tid;            // node q, u32 slot c
        int q = idx / 48, c = idx - q * 48;
        int ch = (c < 24) ? c * 2 : (c - 24) * 2;
        float rm = s_rmn[q];
        float v0 = s[q * 49 + ch]     * rm;
        float v1 = s[q * 49 + ch + 1] * rm;
        __half h0 = __float2half_rn(v0);
        __half h1 = __float2half_rn(v1);
        __half2 outp;
        if (c < 24) outp = __halves2half2(h0, h1);
        else        outp = __halves2half2(__float2half_rn(v0 - __half2float(h0)),
                                          __float2half_rn(v1 - __half2float(h1)));
        g_h16[(size_t)(n0g + q) * 48 + c] = *(uint32_t*)&outp;
    }
}

// ======================================================================
// K2: Gram via mma.sync fp16-split (ah*bh + ah*bl + al*bh, one fp32 acc)
//     + register-resident top-9 per (row, col-slice) with min-fold screen.
// ======================================================================
__global__ __launch_bounds__(256, 2) void k2_knn() {
    extern __shared__ __align__(16) char smem[];
    const uint32_t sb = smem_u32(smem);
    const int tid  = threadIdx.x;
    const int wid  = tid >> 5;
    const int lane = tid & 31;
    const int g    = lane >> 2;
    const int tig  = lane & 3;
    const int b    = blockIdx.x >> 5;
    const int rt   = blockIdx.x & 31;
    const int rowbase = b * NPIX + rt * 128;

    // ldmatrix per-lane base addresses (240B row stride: conflict-free)
    const int arow = ((lane >> 3) & 1) * 8 + (lane & 7);
    const int akof = ((lane >> 4) & 1) * 8;
    const uint32_t aBase = sb + OFF_A + (uint32_t)(wid * 16 + arow) * 240 + akof * 2;
    const int brow = ((lane >> 4) & 1) * 8 + (lane & 7);
    const int bkof = ((lane >> 3) & 1) * 8;
    const uint32_t bBase = sb + OFF_B + (uint32_t)brow * 240 + bkof * 2;

    // prologue: A tile + B tile 0 + sq0
    {
        const char* hsrc = (const char*)g_h16;
        #pragma unroll
        for (int i = 0; i < 6; i++) {
            int lin = tid + i * 256;                  // 1536 chunks of 16B
            int row = lin / 12, c = lin - row * 12;
            cp16(sb + OFF_A + row * 240 + c * 16,
                 hsrc + (size_t)(rowbase + row) * 192 + c * 16);
            cp16(sb + OFF_B + row * 240 + c * 16,
                 hsrc + (size_t)(b * NPIX + row) * 192 + c * 16);
        }
        if (tid < 128) cp4(sb + OFF_SQ + tid * 4, g_sq + b * NPIX + tid);
        cp_commit();
    }

    // register top-9 lists: row A (g) and row B (g+8), this thread's 32 cols
    float d9A[KNN], d9B[KNN]; int i9A[KNN], i9B[KNN];
    #pragma unroll
    for (int k = 0; k < KNN; k++) {
        d9A[k] = __int_as_float(0x7f800000); i9A[k] = 0x7fffffff;
        d9B[k] = __int_as_float(0x7f800000); i9B[k] = 0x7fffffff;
    }

    #pragma unroll 1
    for (int t = 0; t < 32; t++) {
        const int buf = t & 1;
        cp_wait<0>();
        __syncthreads();

        if (t < 31) {
            const int cb = b * NPIX + (t + 1) * 128;
            const char* hsrc = (const char*)g_h16;
            const uint32_t dstB = sb + OFF_B + (buf ^ 1) * 30720;
            #pragma unroll
            for (int i = 0; i < 6; i++) {
                int lin = tid + i * 256;
                int row = lin / 12, c = lin - row * 12;
                cp16(dstB + row * 240 + c * 16,
                     hsrc + (size_t)(cb + row) * 192 + c * 16);
            }
            if (tid < 128) cp4(sb + OFF_SQ + (buf ^ 1) * 512 + tid * 4, g_sq + cb + tid);
            cp_commit();
        }

        // ---- GEMM: 9 k16 chunks (ah*bh, ah*bl, al*bh), 8 np-blocks of 16 cols ----
        float C[64];
        #pragma unroll
        for (int i = 0; i < 64; i++) C[i] = 0.f;
        const uint32_t bBuf = bBase + buf * 30720;
        #pragma unroll
        for (int c9 = 0; c9 < 9; c9++) {
            const int seg = c9 / 3, kc = c9 - seg * 3;
            const int ac = (seg < 2 ? 0 : 48) + kc * 16;
            const int bc = (seg == 1 ? 48 : 0) + kc * 16;
            uint32_t a[4];
            ldsm4(a, aBase + ac * 2);
            #pragma unroll
            for (int np = 0; np < 8; np++) {
                uint32_t bb[4];
                ldsm4(bb, bBuf + np * 3840 + bc * 2);
                mma16816(C + np * 8,     a, bb[0], bb[1]);
                mma16816(C + np * 8 + 4, a, bb[2], bb[3]);
            }
        }

        // ---- epilogue: min-fold screen per row, rare recompute+insert ----
        const char* sqb = smem + OFF_SQ + buf * 512;
        const int colbase = b * NPIX + t * 128 + tig * 2;
        float mnA = __int_as_float(0x7f800000);
        float mnB = __int_as_float(0x7f800000);
        #pragma unroll
        for (int nb = 0; nb < 16; nb++) {
            const float2 s2 = *(const float2*)(sqb + (nb * 8 + tig * 2) * 4);
            const float dA0 = fmaf(-2.f, C[nb * 4 + 0], s2.x);
            const float dA1 = fmaf(-2.f, C[nb * 4 + 1], s2.y);
            const float dB0 = fmaf(-2.f, C[nb * 4 + 2], s2.x);
            const float dB1 = fmaf(-2.f, C[nb * 4 + 3], s2.y);
            mnA = fminf(mnA, fminf(dA0, dA1));
            mnB = fminf(mnB, fminf(dB0, dB1));
        }
        if (mnA < d9A[KNN - 1]) {
            #pragma unroll
            for (int nb = 0; nb < 16; nb++) {
                const float2 s2 = *(const float2*)(sqb + (nb * 8 + tig * 2) * 4);
                const float dv0 = fmaf(-2.f, C[nb * 4 + 0], s2.x);
                const float dv1 = fmaf(-2.f, C[nb * 4 + 1], s2.y);
                if (dv0 < d9A[KNN - 1]) rins(d9A, i9A, dv0, colbase + nb * 8);
                if (dv1 < d9A[KNN - 1]) rins(d9A, i9A, dv1, colbase + nb * 8 + 1);
            }
        }
        if (mnB < d9B[KNN - 1]) {
            #pragma unroll
            for (int nb = 0; nb < 16; nb++) {
                const float2 s2 = *(const float2*)(sqb + (nb * 8 + tig * 2) * 4);
                const float dv0 = fmaf(-2.f, C[nb * 4 + 2], s2.x);
                const float dv1 = fmaf(-2.f, C[nb * 4 + 3], s2.y);
                if (dv0 < d9B[KNN - 1]) rins(d9B, i9B, dv0, colbase + nb * 8);
                if (dv1 < d9B[KNN - 1]) rins(d9B, i9B, dv1, colbase + nb * 8 + 1);
            }
        }
    }

    // ---- writeout: candidate lists [row][tig][9] ----
    const int rowA = rowbase + wid * 16 + g;
    const int rowB = rowA + 8;
    #pragma unroll
    for (int k = 0; k < KNN; k++) {
        g_candi[(size_t)rowA * 36 + tig * 9 + k] = i9A[k];
        g_candi[(size_t)rowB * 36 + tig * 9 + k] = i9B[k];
    }
}

// ======================================================================
// K3: exact fp32 rerank of the 36 slice candidates -> g_knn + degrees.
// One 64-thread block per row (slices partition columns: no duplicates).
// ======================================================================
__global__ __launch_bounds__(64) void k3_rerank() {
    const int row = blockIdx.x;
    const int t = threadIdx.x;
    __shared__ float s_row[48];
    __shared__ float s_d[36];
    __shared__ int   s_i[36];

    if (t < 12) ((float4*)s_row)[t] = g_xn[(size_t)row * 12 + t];
    __syncthreads();

    float d = 0.f; int idx = 0;
    if (t < 36) {
        idx = g_candi[(size_t)row * 36 + t];
        const float4* cv = g_xn + (size_t)idx * 12;
        float acc = 0.f;
        #pragma unroll
        for (int q = 0; q < 12; q++) {
            const float4 v = cv[q];
            acc += s_row[4 * q + 0] * v.x + s_row[4 * q + 1] * v.y
                 + s_row[4 * q + 2] * v.z + s_row[4 * q + 3] * v.w;
        }
        d = fmaf(-2.f, acc, g_sq[idx]);
        s_d[t] = d; s_i[t] = idx;
    }
    __syncthreads();

    if (t < 36) {
        int rank = 0;
        #pragma unroll 6
        for (int o = 0; o < 36; o++) {
            const float od = s_d[o]; const int oi = s_i[o];
            rank += (od < d) || (od == d && oi < idx);
        }
        if (rank < KNN) {
            g_knn[(size_t)row * KNN + rank] = idx;
            if (!(row == NB - 1 && rank == KNN - 1))
                atomicAdd(&g_deg[idx], 1);
        }
    }
}

// ======================================================================
// K5: fused Tx1 gather + both GEMMs + bias.
// ======================================================================
__global__ __launch_bounds__(192) void k5_output(const float* __restrict__ W0,
                                                 const float* __restrict__ W1,
                                                 const float* __restrict__ bias,
                                                 float* __restrict__ out) {
    const int node0 = blockIdx.x * 4;
    const int ln = threadIdx.x / 48;
    const int c  = threadIdx.x - ln * 48;
    const int i  = node0 + ln;

    __shared__ float t1[4][48];
    __shared__ int   ssrc[4][KNN];
    __shared__ float sdi[4][KNN];

    if (threadIdx.x < 4 * KNN) {
        const int l = threadIdx.x / KNN, k = threadIdx.x - l * KNN;
        const int e = (node0 + l) * KNN + k;
        const int s = g_knn[e];
        ssrc[l][k] = s;
        float di = 0.f;
        const int dg = g_deg[s];
        if (dg > 0 && e != NB * KNN - 1) di = rsqrtf((float)dg);
        sdi[l][k] = di;
    }
    __syncthreads();

    const float* nodes = (const float*)g_nodes;
    float acc = 0.f;
    #pragma unroll
    for (int k = 0; k < KNN; k++)
        acc += sdi[ln][k] * nodes[(size_t)ssrc[ln][k] * 48 + c];

    const int dgi = g_deg[i];
    const float dinv_i = (dgi > 0) ? rsqrtf((float)dgi) : 0.f;
    t1[ln][c] = -dinv_i * acc;
    __syncthreads();

    float o = bias[c];
    const float* nrow = nodes + (size_t)i * 48;
    #pragma unroll
    for (int cc = 0; cc < 48; cc++)
        o += nrow[cc] * W0[cc * 48 + c] + t1[ln][cc] * W1[cc * 48 + c];
    out[(size_t)i * 48 + c] = o;
}

// ======================================================================
extern "C" void kernel_launch(void* const* d_in, const int* in_sizes, int n_in,
                              void* d_out, int out_size) {
    const float* x    = (const float*)d_in[0];
    const float* W0   = (const float*)d_in[1];
    const float* W1   = (const float*)d_in[2];
    const float* bias = (const float*)d_in[3];
    float* out = (float*)d_out;

    cudaFuncSetAttribute(k2_knn, cudaFuncAttributeMaxDynamicSharedMemorySize, SMEM_K2);

    k1_normalize<<<NB / 128, 128>>>(x);
    k2_knn<<<BATCH * 32, 256, SMEM_K2>>>();
    k3_rerank<<<NB, 64>>>();
    k5_output<<<NB / 4, 192>>>(W0, W1, bias, out);
}

// round 13
// speedup vs baseline: 1.5663x; 1.1653x over previous
#include <cuda_runtime.h>
#include <cuda_fp16.h>
#include <cstdint>

#define BATCH 8
#define CCH   48
#define NPIX  4096
#define NB    32768
#define KNN   9

// ---------------- device scratch ----------------
__device__ float4   g_xn[NB * 12];     // normalized fp32 (exact rerank)
__device__ float4   g_nodes[NB * 12];  // raw (k5)
__device__ float    g_sq[NB];          // sum(xn^2)
__device__ uint32_t g_h16[NB * 24];    // per node: 24 half2 (hi only, 96B)
__device__ int      g_candi[NB * 36];  // [row][tig 0..3][9]
__device__ int      g_knn[NB * KNN];
__device__ int      g_deg[NB];

// ---------------- helpers ----------------
__device__ __forceinline__ uint32_t smem_u32(const void* p) {
    uint32_t a;
    asm("{ .reg .u64 t; cvta.to.shared.u64 t, %1; cvt.u32.u64 %0, t; }" : "=r"(a) : "l"(p));
    return a;
}
__device__ __forceinline__ void cp16(uint32_t dst, const void* src) {
    asm volatile("cp.async.cg.shared.global [%0], [%1], 16;" :: "r"(dst), "l"(src));
}
__device__ __forceinline__ void cp4(uint32_t dst, const void* src) {
    asm volatile("cp.async.ca.shared.global [%0], [%1], 4;" :: "r"(dst), "l"(src));
}
__device__ __forceinline__ void cp_commit() { asm volatile("cp.async.commit_group;"); }
template <int N> __device__ __forceinline__ void cp_wait() {
    asm volatile("cp.async.wait_group %0;" :: "n"(N));
}
__device__ __forceinline__ void ldsm4(uint32_t* R, uint32_t addr) {
    asm volatile("ldmatrix.sync.aligned.m8n8.x4.shared.b16 {%0,%1,%2,%3}, [%4];"
                 : "=r"(R[0]), "=r"(R[1]), "=r"(R[2]), "=r"(R[3]) : "r"(addr));
}
__device__ __forceinline__ void mma16816(float* C, const uint32_t* A, uint32_t b0, uint32_t b1) {
    asm volatile("mma.sync.aligned.m16n8k16.row.col.f32.f16.f16.f32 "
                 "{%0,%1,%2,%3}, {%4,%5,%6,%7}, {%8,%9}, {%0,%1,%2,%3};"
                 : "+f"(C[0]), "+f"(C[1]), "+f"(C[2]), "+f"(C[3])
                 : "r"(A[0]), "r"(A[1]), "r"(A[2]), "r"(A[3]), "r"(b0), "r"(b1));
}
// register carry-chain sorted insert (strict <, ascending-col call order)
__device__ __forceinline__ void rins(float* d9, int* i9, float d, int idx) {
    float cd = d; int ci = idx;
    #pragma unroll
    for (int sl = 0; sl < KNN; sl++) {
        const bool sw = cd < d9[sl];
        const float td = d9[sl]; const int ti = i9[sl];
        d9[sl] = sw ? cd : td;  i9[sl] = sw ? ci : ti;
        cd     = sw ? td : cd;  ci     = sw ? ti : ci;
    }
}

// ---------------- k2 smem layout (bytes) ----------------
// 112B row stride: r*112 mod 128 = {0,112,96,80,64,48,32,16} => ldsm conflict-free
#define OFF_A   0                      // A tile: 128 rows x 112B = 14336
#define OFF_B   14336                  // 2 x 14336
#define OFF_SQ  43008                  // 2 x 512
#define SMEM_K2 44032

// ======================================================================
// K1: normalize; emit g_xn (fp32), g_nodes, g_sq, fp16 hi, deg=0.
// ======================================================================
__global__ __launch_bounds__(128) void k1_normalize(const float* __restrict__ x) {
    __shared__ float s[128 * 49];
    __shared__ float s_mn[128];
    __shared__ float s_rmn[128];
    const int tid  = threadIdx.x;
    const int n0g  = blockIdx.x * 128;
    const int b    = n0g >> 12;
    const int nloc = n0g & (NPIX - 1);

    const float* xb = x + (size_t)b * CCH * NPIX + nloc;
    #pragma unroll
    for (int c = 0; c < CCH; c++)
        s[tid * 49 + c] = xb[(size_t)c * NPIX + tid];

    float ss = 0.f;
    #pragma unroll
    for (int c = 0; c < CCH; c++) { float v = s[tid * 49 + c]; ss += v * v; }
    float mn = fmaxf(sqrtf(ss), 1e-12f);
    s_mn[tid]  = mn;
    s_rmn[tid] = 1.0f / mn;
    float sqv = 0.f;
    #pragma unroll
    for (int c = 0; c < CCH; c++) { float v = s[tid * 49 + c] / mn; sqv += v * v; }
    g_sq[n0g + tid]  = sqv;
    g_deg[n0g + tid] = 0;
    __syncthreads();

    float* nodes_f = (float*)g_nodes;
    float* xn_f    = (float*)g_xn;
    #pragma unroll
    for (int it = 0; it < 48; it++) {
        int idx = it * 128 + tid;
        int q = idx / 48, rr = idx - q * 48;
        float v = s[q * 49 + rr];
        nodes_f[(size_t)n0g * 48 + idx] = v;
        xn_f[(size_t)n0g * 48 + idx]    = v / s_mn[q];
    }
    // fp16 hi only (screening path)
    #pragma unroll
    for (int it = 0; it < 24; it++) {
        int idx = it * 128 + tid;            // node q, half2 slot c
        int q = idx / 24, c = idx - q * 24;
        float rm = s_rmn[q];
        __half2 hp = __halves2half2(__float2half_rn(s[q * 49 + 2 * c]     * rm),
                                    __float2half_rn(s[q * 49 + 2 * c + 1] * rm));
        g_h16[(size_t)(n0g + q) * 24 + c] = *(uint32_t*)&hp;
    }
}

// ======================================================================
// K2: Gram screen via fp16 mma.sync (hi only, K=48, 3 k16 chunks)
//     + register-resident top-9 per (row, col-slice) with min-fold screen.
// ======================================================================
__global__ __launch_bounds__(256, 2) void k2_knn() {
    extern __shared__ __align__(16) char smem[];
    const uint32_t sb = smem_u32(smem);
    const int tid  = threadIdx.x;
    const int wid  = tid >> 5;
    const int lane = tid & 31;
    const int g    = lane >> 2;
    const int tig  = lane & 3;
    const int b    = blockIdx.x >> 5;
    const int rt   = blockIdx.x & 31;
    const int rowbase = b * NPIX + rt * 128;

    // ldmatrix per-lane base addresses
    const int arow = ((lane >> 3) & 1) * 8 + (lane & 7);
    const int akof = ((lane >> 4) & 1) * 8;
    const uint32_t aBase = sb + OFF_A + (uint32_t)(wid * 16 + arow) * 112 + akof * 2;
    const int brow = ((lane >> 4) & 1) * 8 + (lane & 7);
    const int bkof = ((lane >> 3) & 1) * 8;
    const uint32_t bBase = sb + OFF_B + (uint32_t)brow * 112 + bkof * 2;

    // prologue: A tile + B tile 0 + sq0
    {
        const char* hsrc = (const char*)g_h16;
        #pragma unroll
        for (int i = 0; i < 3; i++) {
            int lin = tid + i * 256;                  // 768 chunks of 16B
            int row = lin / 6, c = lin - row * 6;
            cp16(sb + OFF_A + row * 112 + c * 16,
                 hsrc + (size_t)(rowbase + row) * 96 + c * 16);
            cp16(sb + OFF_B + row * 112 + c * 16,
                 hsrc + (size_t)(b * NPIX + row) * 96 + c * 16);
        }
        if (tid < 128) cp4(sb + OFF_SQ + tid * 4, g_sq + b * NPIX + tid);
        cp_commit();
    }

    // register top-9 lists: row A (g) and row B (g+8), this thread's 32 cols
    float d9A[KNN], d9B[KNN]; int i9A[KNN], i9B[KNN];
    #pragma unroll
    for (int k = 0; k < KNN; k++) {
        d9A[k] = __int_as_float(0x7f800000); i9A[k] = 0x7fffffff;
        d9B[k] = __int_as_float(0x7f800000); i9B[k] = 0x7fffffff;
    }

    #pragma unroll 1
    for (int t = 0; t < 32; t++) {
        const int buf = t & 1;
        cp_wait<0>();
        __syncthreads();

        if (t < 31) {
            const int cb = b * NPIX + (t + 1) * 128;
            const char* hsrc = (const char*)g_h16;
            const uint32_t dstB = sb + OFF_B + (buf ^ 1) * 14336;
            #pragma unroll
            for (int i = 0; i < 3; i++) {
                int lin = tid + i * 256;
                int row = lin / 6, c = lin - row * 6;
                cp16(dstB + row * 112 + c * 16,
                     hsrc + (size_t)(cb + row) * 96 + c * 16);
            }
            if (tid < 128) cp4(sb + OFF_SQ + (buf ^ 1) * 512 + tid * 4, g_sq + cb + tid);
            cp_commit();
        }

        // ---- GEMM: 3 k16 chunks, 8 np-blocks of 16 cols ----
        float C[64];
        #pragma unroll
        for (int i = 0; i < 64; i++) C[i] = 0.f;
        const uint32_t bBuf = bBase + buf * 14336;
        #pragma unroll
        for (int kc = 0; kc < 3; kc++) {
            uint32_t a[4];
            ldsm4(a, aBase + kc * 32);
            #pragma unroll
            for (int np = 0; np < 8; np++) {
                uint32_t bb[4];
                ldsm4(bb, bBuf + np * 1792 + kc * 32);
                mma16816(C + np * 8,     a, bb[0], bb[1]);
                mma16816(C + np * 8 + 4, a, bb[2], bb[3]);
            }
        }

        // ---- epilogue: min-fold screen per row, rare recompute+insert ----
        const char* sqb = smem + OFF_SQ + buf * 512;
        const int colbase = b * NPIX + t * 128 + tig * 2;
        float mnA = __int_as_float(0x7f800000);
        float mnB = __int_as_float(0x7f800000);
        #pragma unroll
        for (int nb = 0; nb < 16; nb++) {
            const float2 s2 = *(const float2*)(sqb + (nb * 8 + tig * 2) * 4);
            const float dA0 = fmaf(-2.f, C[nb * 4 + 0], s2.x);
            const float dA1 = fmaf(-2.f, C[nb * 4 + 1], s2.y);
            const float dB0 = fmaf(-2.f, C[nb * 4 + 2], s2.x);
            const float dB1 = fmaf(-2.f, C[nb * 4 + 3], s2.y);
            mnA = fminf(mnA, fminf(dA0, dA1));
            mnB = fminf(mnB, fminf(dB0, dB1));
        }
        if (mnA < d9A[KNN - 1]) {
            #pragma unroll
            for (int nb = 0; nb < 16; nb++) {
                const float2 s2 = *(const float2*)(sqb + (nb * 8 + tig * 2) * 4);
                const float dv0 = fmaf(-2.f, C[nb * 4 + 0], s2.x);
                const float dv1 = fmaf(-2.f, C[nb * 4 + 1], s2.y);
                if (dv0 < d9A[KNN - 1]) rins(d9A, i9A, dv0, colbase + nb * 8);
                if (dv1 < d9A[KNN - 1]) rins(d9A, i9A, dv1, colbase + nb * 8 + 1);
            }
        }
        if (mnB < d9B[KNN - 1]) {
            #pragma unroll
            for (int nb = 0; nb < 16; nb++) {
                const float2 s2 = *(const float2*)(sqb + (nb * 8 + tig * 2) * 4);
                const float dv0 = fmaf(-2.f, C[nb * 4 + 2], s2.x);
                const float dv1 = fmaf(-2.f, C[nb * 4 + 3], s2.y);
                if (dv0 < d9B[KNN - 1]) rins(d9B, i9B, dv0, colbase + nb * 8);
                if (dv1 < d9B[KNN - 1]) rins(d9B, i9B, dv1, colbase + nb * 8 + 1);
            }
        }
    }

    // ---- writeout: candidate lists [row][tig][9] ----
    const int rowA = rowbase + wid * 16 + g;
    const int rowB = rowA + 8;
    #pragma unroll
    for (int k = 0; k < KNN; k++) {
        g_candi[(size_t)rowA * 36 + tig * 9 + k] = i9A[k];
        g_candi[(size_t)rowB * 36 + tig * 9 + k] = i9B[k];
    }
}

// ======================================================================
// K3: exact fp32 rerank of the 36 slice candidates -> g_knn + degrees.
// ======================================================================
__global__ __launch_bounds__(64) void k3_rerank() {
    const int row = blockIdx.x;
    const int t = threadIdx.x;
    __shared__ float s_row[48];
    __shared__ float s_d[36];
    __shared__ int   s_i[36];

    if (t < 12) ((float4*)s_row)[t] = g_xn[(size_t)row * 12 + t];
    __syncthreads();

    float d = 0.f; int idx = 0;
    if (t < 36) {
        idx = g_candi[(size_t)row * 36 + t];
        const float4* cv = g_xn + (size_t)idx * 12;
        float acc = 0.f;
        #pragma unroll
        for (int q = 0; q < 12; q++) {
            const float4 v = cv[q];
            acc += s_row[4 * q + 0] * v.x + s_row[4 * q + 1] * v.y
                 + s_row[4 * q + 2] * v.z + s_row[4 * q + 3] * v.w;
        }
        d = fmaf(-2.f, acc, g_sq[idx]);
        s_d[t] = d; s_i[t] = idx;
    }
    __syncthreads();

    if (t < 36) {
        int rank = 0;
        #pragma unroll 6
        for (int o = 0; o < 36; o++) {
            const float od = s_d[o]; const int oi = s_i[o];
            rank += (od < d) || (od == d && oi < idx);
        }
        if (rank < KNN) {
            g_knn[(size_t)row * KNN + rank] = idx;
            if (!(row == NB - 1 && rank == KNN - 1))
                atomicAdd(&g_deg[idx], 1);
        }
    }
}

// ======================================================================
// K5: fused Tx1 gather + both GEMMs + bias; weights staged in smem.
// 8 nodes per block, 384 threads.
// ======================================================================
__global__ __launch_bounds__(384) void k5_output(const float* __restrict__ W0,
                                                 const float* __restrict__ W1,
                                                 const float* __restrict__ bias,
                                                 float* __restrict__ out) {
    __shared__ float sW0[48 * 48];
    __shared__ float sW1[48 * 48];
    __shared__ float sbv[48];
    __shared__ float t0[8][48];
    __shared__ float t1[8][48];
    __shared__ int   ssrc[8][KNN];
    __shared__ float sdi[8][KNN];

    const int tid = threadIdx.x;
    const int node0 = blockIdx.x * 8;
    const int ln = tid / 48;
    const int c  = tid - ln * 48;
    const int i  = node0 + ln;

    for (int j = tid; j < 2304; j += 384) { sW0[j] = W0[j]; sW1[j] = W1[j]; }
    if (tid < 48) sbv[tid] = bias[tid];
    if (tid < 8 * KNN) {
        const int l = tid / KNN, k = tid - l * KNN;
        const int e = (node0 + l) * KNN + k;
        const int s = g_knn[e];
        ssrc[l][k] = s;
        float di = 0.f;
        const int dg = g_deg[s];
        if (dg > 0 && e != NB * KNN - 1) di = rsqrtf((float)dg);
        sdi[l][k] = di;
    }
    __syncthreads();

    const float* nodes = (const float*)g_nodes;
    float acc = 0.f;
    #pragma unroll
    for (int k = 0; k < KNN; k++)
        acc += sdi[ln][k] * nodes[(size_t)ssrc[ln][k] * 48 + c];

    const int dgi = g_deg[i];
    const float dinv_i = (dgi > 0) ? rsqrtf((float)dgi) : 0.f;
    t1[ln][c] = -dinv_i * acc;
    t0[ln][c] = nodes[(size_t)i * 48 + c];
    __syncthreads();

    float o = sbv[c];
    #pragma unroll
    for (int cc = 0; cc < 48; cc++)
        o += t0[ln][cc] * sW0[cc * 48 + c] + t1[ln][cc] * sW1[cc * 48 + c];
    out[(size_t)i * 48 + c] = o;
}

// ======================================================================
extern "C" void kernel_launch(void* const* d_in, const int* in_sizes, int n_in,
                              void* d_out, int out_size) {
    const float* x    = (const float*)d_in[0];
    const float* W0   = (const float*)d_in[1];
    const float* W1   = (const float*)d_in[2];
    const float* bias = (const float*)d_in[3];
    float* out = (float*)d_out;

    cudaFuncSetAttribute(k2_knn, cudaFuncAttributeMaxDynamicSharedMemorySize, SMEM_K2);

    k1_normalize<<<NB / 128, 128>>>(x);
    k2_knn<<<BATCH * 32, 256, SMEM_K2>>>();
    k3_rerank<<<NB, 64>>>();
    k5_output<<<NB / 8, 384>>>(W0, W1, bias, out);
}

// round 14
// speedup vs baseline: 1.6404x; 1.0473x over previous
#include <cuda_runtime.h>
#include <cuda_fp16.h>
#include <cstdint>

#define BATCH 8
#define CCH   48
#define NPIX  4096
#define NB    32768
#define KNN   9

// ---------------- device scratch ----------------
__device__ float4   g_xn[NB * 12];     // normalized fp32 (exact rerank)
__device__ float4   g_nodes[NB * 12];  // raw (k5)
__device__ float    g_sq[NB];          // sum(xn^2)
__device__ uint32_t g_h16[NB * 28];    // per node: 24 half2 hi + 4 pad (112B rows)
__device__ int      g_candi[NB * 36];  // [row][tig 0..3][9]
__device__ int      g_knn[NB * KNN];
__device__ int      g_deg[NB];

// ---------------- helpers ----------------
__device__ __forceinline__ uint32_t smem_u32(const void* p) {
    uint32_t a;
    asm("{ .reg .u64 t; cvta.to.shared.u64 t, %1; cvt.u32.u64 %0, t; }" : "=r"(a) : "l"(p));
    return a;
}
__device__ __forceinline__ void bulkcp(uint32_t dst, const void* src, uint32_t bytes,
                                       uint32_t mbar) {
    asm volatile("cp.async.bulk.shared::cta.global.mbarrier::complete_tx::bytes "
                 "[%0], [%1], %2, [%3];"
                 :: "r"(dst), "l"(src), "r"(bytes), "r"(mbar) : "memory");
}
#define MBAR_INIT(a, c) \
    asm volatile("mbarrier.init.shared.b64 [%0], %1;" :: "r"(a), "r"(c) : "memory")
#define MBAR_EXPECT(a, bytes) \
    asm volatile("mbarrier.arrive.expect_tx.shared.b64 _, [%0], %1;" \
                 :: "r"(a), "r"((uint32_t)(bytes)) : "memory")
#define FENCE_ASYNC() asm volatile("fence.proxy.async.shared::cta;" ::: "memory")
#define MBAR_WAIT(a, ph) do {                                                     \
    uint32_t _m = (a); uint32_t _p = (uint32_t)(ph); uint32_t _done;              \
    asm volatile("{\n\t.reg .pred p;\n\t"                                         \
        "mbarrier.try_wait.parity.acquire.cta.shared::cta.b64 p, [%1], %2;\n\t"   \
        "selp.b32 %0, 1, 0, p;\n\t}" : "=r"(_done) : "r"(_m), "r"(_p) : "memory");\
    if (!_done) {                                                                 \
        asm volatile("{\n\t.reg .pred P1;\n\tWL_%=:\n\t"                          \
            "mbarrier.try_wait.parity.acquire.cta.shared::cta.b64 P1, [%0], %1, 0x989680;\n\t" \
            "@P1 bra.uni WD_%=;\n\tbra.uni WL_%=;\n\tWD_%=:\n\t}"                 \
            :: "r"(_m), "r"(_p) : "memory");                                      \
    } } while (0)

__device__ __forceinline__ void ldsm4(uint32_t* R, uint32_t addr) {
    asm volatile("ldmatrix.sync.aligned.m8n8.x4.shared.b16 {%0,%1,%2,%3}, [%4];"
                 : "=r"(R[0]), "=r"(R[1]), "=r"(R[2]), "=r"(R[3]) : "r"(addr));
}
__device__ __forceinline__ void mma16816(float* C, const uint32_t* A, uint32_t b0, uint32_t b1) {
    asm volatile("mma.sync.aligned.m16n8k16.row.col.f32.f16.f16.f32 "
                 "{%0,%1,%2,%3}, {%4,%5,%6,%7}, {%8,%9}, {%0,%1,%2,%3};"
                 : "+f"(C[0]), "+f"(C[1]), "+f"(C[2]), "+f"(C[3])
                 : "r"(A[0]), "r"(A[1]), "r"(A[2]), "r"(A[3]), "r"(b0), "r"(b1));
}
__device__ __forceinline__ void rins(float* d9, int* i9, float d, int idx) {
    float cd = d; int ci = idx;
    #pragma unroll
    for (int sl = 0; sl < KNN; sl++) {
        const bool sw = cd < d9[sl];
        const float td = d9[sl]; const int ti = i9[sl];
        d9[sl] = sw ? cd : td;  i9[sl] = sw ? ci : ti;
        cd     = sw ? td : cd;  ci     = sw ? ti : ci;
    }
}

// ---------------- k2 smem layout (bytes) ----------------
// 112B row stride: r*112 mod 128 cycles {0,112,96,80,64,48,32,16} => ldsm conflict-free
#define OFF_A   0                      // A tile: 128 x 112B = 14336
#define OFF_B   14336                  // 2 x 14336
#define OFF_SQ  43008                  // 2 x 512
#define OFF_MB  44032                  // 2 mbarriers
#define SMEM_K2 44048

// ======================================================================
// K1: normalize; emit g_xn (fp32), g_nodes, g_sq, fp16 hi (112B rows), deg=0.
// ======================================================================
__global__ __launch_bounds__(128) void k1_normalize(const float* __restrict__ x) {
    __shared__ float s[128 * 49];
    __shared__ float s_mn[128];
    __shared__ float s_rmn[128];
    const int tid  = threadIdx.x;
    const int n0g  = blockIdx.x * 128;
    const int b    = n0g >> 12;
    const int nloc = n0g & (NPIX - 1);

    const float* xb = x + (size_t)b * CCH * NPIX + nloc;
    #pragma unroll
    for (int c = 0; c < CCH; c++)
        s[tid * 49 + c] = xb[(size_t)c * NPIX + tid];

    float ss = 0.f;
    #pragma unroll
    for (int c = 0; c < CCH; c++) { float v = s[tid * 49 + c]; ss += v * v; }
    float mn = fmaxf(sqrtf(ss), 1e-12f);
    s_mn[tid]  = mn;
    s_rmn[tid] = 1.0f / mn;
    float sqv = 0.f;
    #pragma unroll
    for (int c = 0; c < CCH; c++) { float v = s[tid * 49 + c] / mn; sqv += v * v; }
    g_sq[n0g + tid]  = sqv;
    g_deg[n0g + tid] = 0;
    __syncthreads();

    float* nodes_f = (float*)g_nodes;
    float* xn_f    = (float*)g_xn;
    #pragma unroll
    for (int it = 0; it < 48; it++) {
        int idx = it * 128 + tid;
        int q = idx / 48, rr = idx - q * 48;
        float v = s[q * 49 + rr];
        nodes_f[(size_t)n0g * 48 + idx] = v;
        xn_f[(size_t)n0g * 48 + idx]    = v / s_mn[q];
    }
    // fp16 hi (screening path), 112B global rows (pad slots 24..27 untouched)
    #pragma unroll
    for (int it = 0; it < 24; it++) {
        int idx = it * 128 + tid;            // node q, half2 slot c
        int q = idx / 24, c = idx - q * 24;
        float rm = s_rmn[q];
        __half2 hp = __halves2half2(__float2half_rn(s[q * 49 + 2 * c]     * rm),
                                    __float2half_rn(s[q * 49 + 2 * c + 1] * rm));
        g_h16[(size_t)(n0g + q) * 28 + c] = *(uint32_t*)&hp;
    }
    // zero pad slots (deterministic smem contents)
    #pragma unroll
    for (int it = 0; it < 4; it++) {
        int idx = it * 128 + tid;            // 512 = 128 nodes x 4 pad slots
        int q = idx >> 2, c = idx & 3;
        g_h16[(size_t)(n0g + q) * 28 + 24 + c] = 0u;
    }
}

// ======================================================================
// K2: fp16 hi-only Gram screen via mma.sync; tiles loaded with
//     cp.async.bulk + mbarrier (2 ops/tile); register top-9 per slice.
// ======================================================================
__global__ __launch_bounds__(256, 2) void k2_knn() {
    extern __shared__ __align__(16) char smem[];
    const uint32_t sb = smem_u32(smem);
    const int tid  = threadIdx.x;
    const int wid  = tid >> 5;
    const int lane = tid & 31;
    const int g    = lane >> 2;
    const int tig  = lane & 3;
    const int b    = blockIdx.x >> 5;
    const int rt   = blockIdx.x & 31;
    const int rowbase = b * NPIX + rt * 128;

    // ldmatrix per-lane base addresses (112B stride, conflict-free)
    const int arow = ((lane >> 3) & 1) * 8 + (lane & 7);
    const int akof = ((lane >> 4) & 1) * 8;
    const uint32_t aBase = sb + OFF_A + (uint32_t)(wid * 16 + arow) * 112 + akof * 2;
    const int brow = ((lane >> 4) & 1) * 8 + (lane & 7);
    const int bkof = ((lane >> 3) & 1) * 8;
    const uint32_t bBase = sb + OFF_B + (uint32_t)brow * 112 + bkof * 2;

    const char* hsrc = (const char*)g_h16;

    // mbarrier init + prologue bulk loads (A + B0 + sq0 on mbar0)
    if (tid == 0) {
        MBAR_INIT(sb + OFF_MB, 1);
        MBAR_INIT(sb + OFF_MB + 8, 1);
        FENCE_ASYNC();
    }
    __syncthreads();
    if (tid == 0) {
        MBAR_EXPECT(sb + OFF_MB, 14336 + 14336 + 512);
        bulkcp(sb + OFF_A, hsrc + (size_t)rowbase * 112, 14336, sb + OFF_MB);
        bulkcp(sb + OFF_B, hsrc + (size_t)(b * NPIX) * 112, 14336, sb + OFF_MB);
        bulkcp(sb + OFF_SQ, g_sq + b * NPIX, 512, sb + OFF_MB);
    }

    float d9A[KNN], d9B[KNN]; int i9A[KNN], i9B[KNN];
    #pragma unroll
    for (int k = 0; k < KNN; k++) {
        d9A[k] = __int_as_float(0x7f800000); i9A[k] = 0x7fffffff;
        d9B[k] = __int_as_float(0x7f800000); i9B[k] = 0x7fffffff;
    }

    int ph0 = 0, ph1 = 0;
    #pragma unroll 1
    for (int t = 0; t < 32; t++) {
        const int buf = t & 1;
        __syncthreads();                 // all done reading buffer buf^1 (tile t-1)

        if (t < 31 && tid == 0) {        // prefetch tile t+1
            const int nb = buf ^ 1;
            const uint32_t mb = sb + OFF_MB + nb * 8;
            MBAR_EXPECT(mb, 14336 + 512);
            bulkcp(sb + OFF_B + nb * 14336,
                   hsrc + (size_t)(b * NPIX + (t + 1) * 128) * 112, 14336, mb);
            bulkcp(sb + OFF_SQ + nb * 512, g_sq + b * NPIX + (t + 1) * 128, 512, mb);
        }

        // wait tile t
        if (buf == 0) { MBAR_WAIT(sb + OFF_MB, ph0);     ph0 ^= 1; }
        else          { MBAR_WAIT(sb + OFF_MB + 8, ph1); ph1 ^= 1; }

        // ---- GEMM: 3 k16 chunks, 8 np-blocks of 16 cols ----
        float C[64];
        #pragma unroll
        for (int i = 0; i < 64; i++) C[i] = 0.f;
        const uint32_t bBuf = bBase + buf * 14336;
        #pragma unroll
        for (int kc = 0; kc < 3; kc++) {
            uint32_t a[4];
            ldsm4(a, aBase + kc * 32);
            #pragma unroll
            for (int np = 0; np < 8; np++) {
                uint32_t bb[4];
                ldsm4(bb, bBuf + np * 1792 + kc * 32);
                mma16816(C + np * 8,     a, bb[0], bb[1]);
                mma16816(C + np * 8 + 4, a, bb[2], bb[3]);
            }
        }

        // ---- epilogue: min-fold screen per row, rare recompute+insert ----
        const char* sqb = smem + OFF_SQ + buf * 512;
        const int colbase = b * NPIX + t * 128 + tig * 2;
        float mnA = __int_as_float(0x7f800000);
        float mnB = __int_as_float(0x7f800000);
        #pragma unroll
        for (int nb = 0; nb < 16; nb++) {
            const float2 s2 = *(const float2*)(sqb + (nb * 8 + tig * 2) * 4);
            const float dA0 = fmaf(-2.f, C[nb * 4 + 0], s2.x);
            const float dA1 = fmaf(-2.f, C[nb * 4 + 1], s2.y);
            const float dB0 = fmaf(-2.f, C[nb * 4 + 2], s2.x);
            const float dB1 = fmaf(-2.f, C[nb * 4 + 3], s2.y);
            mnA = fminf(mnA, fminf(dA0, dA1));
            mnB = fminf(mnB, fminf(dB0, dB1));
        }
        if (mnA < d9A[KNN - 1]) {
            #pragma unroll
            for (int nb = 0; nb < 16; nb++) {
                const float2 s2 = *(const float2*)(sqb + (nb * 8 + tig * 2) * 4);
                const float dv0 = fmaf(-2.f, C[nb * 4 + 0], s2.x);
                const float dv1 = fmaf(-2.f, C[nb * 4 + 1], s2.y);
                if (dv0 < d9A[KNN - 1]) rins(d9A, i9A, dv0, colbase + nb * 8);
                if (dv1 < d9A[KNN - 1]) rins(d9A, i9A, dv1, colbase + nb * 8 + 1);
            }
        }
        if (mnB < d9B[KNN - 1]) {
            #pragma unroll
            for (int nb = 0; nb < 16; nb++) {
                const float2 s2 = *(const float2*)(sqb + (nb * 8 + tig * 2) * 4);
                const float dv0 = fmaf(-2.f, C[nb * 4 + 2], s2.x);
                const float dv1 = fmaf(-2.f, C[nb * 4 + 3], s2.y);
                if (dv0 < d9B[KNN - 1]) rins(d9B, i9B, dv0, colbase + nb * 8);
                if (dv1 < d9B[KNN - 1]) rins(d9B, i9B, dv1, colbase + nb * 8 + 1);
            }
        }
    }

    // ---- writeout: candidate lists [row][tig][9] ----
    const int rowA = rowbase + wid * 16 + g;
    const int rowB = rowA + 8;
    #pragma unroll
    for (int k = 0; k < KNN; k++) {
        g_candi[(size_t)rowA * 36 + tig * 9 + k] = i9A[k];
        g_candi[(size_t)rowB * 36 + tig * 9 + k] = i9B[k];
    }
}

// ======================================================================
// K3: exact fp32 rerank of the 36 slice candidates -> g_knn + degrees.
// ======================================================================
__global__ __launch_bounds__(64) void k3_rerank() {
    const int row = blockIdx.x;
    const int t = threadIdx.x;
    __shared__ float s_row[48];
    __shared__ float s_d[36];
    __shared__ int   s_i[36];

    if (t < 12) ((float4*)s_row)[t] = g_xn[(size_t)row * 12 + t];
    __syncthreads();

    float d = 0.f; int idx = 0;
    if (t < 36) {
        idx = g_candi[(size_t)row * 36 + t];
        const float4* cv = g_xn + (size_t)idx * 12;
        float acc = 0.f;
        #pragma unroll
        for (int q = 0; q < 12; q++) {
            const float4 v = cv[q];
            acc += s_row[4 * q + 0] * v.x + s_row[4 * q + 1] * v.y
                 + s_row[4 * q + 2] * v.z + s_row[4 * q + 3] * v.w;
        }
        d = fmaf(-2.f, acc, g_sq[idx]);
        s_d[t] = d; s_i[t] = idx;
    }
    __syncthreads();

    if (t < 36) {
        int rank = 0;
        #pragma unroll 6
        for (int o = 0; o < 36; o++) {
            const float od = s_d[o]; const int oi = s_i[o];
            rank += (od < d) || (od == d && oi < idx);
        }
        if (rank < KNN) {
            g_knn[(size_t)row * KNN + rank] = idx;
            if (!(row == NB - 1 && rank == KNN - 1))
                atomicAdd(&g_deg[idx], 1);
        }
    }
}

// ======================================================================
// K5: fused Tx1 gather + both GEMMs + bias; weights in smem;
//     2 output channels per thread; 16 nodes per 384-thread block.
// ======================================================================
__global__ __launch_bounds__(384) void k5_output(const float* __restrict__ W0,
                                                 const float* __restrict__ W1,
                                                 const float* __restrict__ bias,
                                                 float* __restrict__ out) {
    __shared__ float sW0[48 * 48];
    __shared__ float sW1[48 * 48];
    __shared__ float sbv[48];
    __shared__ float t0[16][48];
    __shared__ float t1[16][48];
    __shared__ int   ssrc[16][KNN];
    __shared__ float sdi[16][KNN];

    const int tid = threadIdx.x;
    const int node0 = blockIdx.x * 16;
    const int ln = tid / 24;          // 0..15
    const int c  = tid - ln * 24;     // 0..23 (owns channels c, c+24)
    const int i  = node0 + ln;

    for (int j = tid; j < 2304; j += 384) { sW0[j] = W0[j]; sW1[j] = W1[j]; }
    if (tid < 48) sbv[tid] = bias[tid];
    if (tid < 16 * KNN) {
        const int l = tid / KNN, k = tid - l * KNN;
        const int e = (node0 + l) * KNN + k;
        const int s = g_knn[e];
        ssrc[l][k] = s;
        float di = 0.f;
        const int dg = g_deg[s];
        if (dg > 0 && e != NB * KNN - 1) di = rsqrtf((float)dg);
        sdi[l][k] = di;
    }
    __syncthreads();

    const float* nodes = (const float*)g_nodes;
    float a0 = 0.f, a1 = 0.f;
    #pragma unroll
    for (int k = 0; k < KNN; k++) {
        const int s48 = ssrc[ln][k] * 48;
        const float di = sdi[ln][k];
        a0 += di * nodes[s48 + c];
        a1 += di * nodes[s48 + c + 24];
    }

    const int dgi = g_deg[i];
    const float dinv_i = (dgi > 0) ? rsqrtf((float)dgi) : 0.f;
    const int i48 = i * 48;
    t1[ln][c]      = -dinv_i * a0;
    t1[ln][c + 24] = -dinv_i * a1;
    t0[ln][c]      = nodes[i48 + c];
    t0[ln][c + 24] = nodes[i48 + c + 24];
    __syncthreads();

    float o0 = sbv[c], o1 = sbv[c + 24];
    #pragma unroll
    for (int cc = 0; cc < 48; cc++) {
        const float v0 = t0[ln][cc];
        const float v1 = t1[ln][cc];
        o0 += v0 * sW0[cc * 48 + c]      + v1 * sW1[cc * 48 + c];
        o1 += v0 * sW0[cc * 48 + c + 24] + v1 * sW1[cc * 48 + c + 24];
    }
    out[i48 + c]      = o0;
    out[i48 + c + 24] = o1;
}

// ======================================================================
extern "C" void kernel_launch(void* const* d_in, const int* in_sizes, int n_in,
                              void* d_out, int out_size) {
    const float* x    = (const float*)d_in[0];
    const float* W0   = (const float*)d_in[1];
    const float* W1   = (const float*)d_in[2];
    const float* bias = (const float*)d_in[3];
    float* out = (float*)d_out;

    cudaFuncSetAttribute(k2_knn, cudaFuncAttributeMaxDynamicSharedMemorySize, SMEM_K2);

    k1_normalize<<<NB / 128, 128>>>(x);
    k2_knn<<<BATCH * 32, 256, SMEM_K2>>>();
    k3_rerank<<<NB, 64>>>();
    k5_output<<<NB / 16, 384>>>(W0, W1, bias, out);
}